// round 13
// baseline (speedup 1.0000x reference)
#include <cuda_runtime.h>
#include <cuda_fp16.h>
#include <math.h>
#include <stdint.h>

// Shapes (fixed by the problem)
#define BB   4
#define TT   2048
#define CC   1024
#define NH   16
#define HD   64
#define MM   (BB*TT)          // 8192
#define N_QKV (3*CC)          // 3072

// ---------------------------------------------------------------------------
// Scratch (device globals; no allocation allowed). All fp16 operands.
// ---------------------------------------------------------------------------
__device__ __half g_Q [BB*NH*TT*HD];   // (B,H,T,D), Q pre-scaled by 1/8
__device__ __half g_K [BB*NH*TT*HD];   // (B,H,T,D)
__device__ __half g_Vt[BB*NH*HD*TT];   // (B,H,D,T)  V TRANSPOSED
__device__ __half g_O [MM*CC];         // (B,T,C) attention out
__device__ __half g_X16[MM*CC];        // fp16 x
__device__ __half g_W1t[N_QKV*CC];     // W_qkv^T [3072][1024]
__device__ __half g_W2t[CC*CC];        // W_out^T [1024][1024]

// ---------------------------------------------------------------------------
// Helpers
// ---------------------------------------------------------------------------
__device__ __forceinline__ uint32_t h2u(__half2 h) {
    uint32_t u;
    *(__half2*)&u = h;
    return u;
}

__device__ __forceinline__ void mma16(float c[4], const uint32_t a[4],
                                      uint32_t b0, uint32_t b1) {
    asm volatile(
        "mma.sync.aligned.m16n8k16.row.col.f32.f16.f16.f32 "
        "{%0,%1,%2,%3},{%4,%5,%6,%7},{%8,%9},{%0,%1,%2,%3};"
        : "+f"(c[0]), "+f"(c[1]), "+f"(c[2]), "+f"(c[3])
        : "r"(a[0]), "r"(a[1]), "r"(a[2]), "r"(a[3]), "r"(b0), "r"(b1));
}

__device__ __forceinline__ void ldsm4(uint32_t r[4], uint32_t addr) {
    asm volatile(
        "ldmatrix.sync.aligned.m8n8.x4.shared.b16 {%0,%1,%2,%3}, [%4];"
        : "=r"(r[0]), "=r"(r[1]), "=r"(r[2]), "=r"(r[3]) : "r"(addr));
}

__device__ __forceinline__ void cp16(uint32_t dst, const void* src) {
    asm volatile("cp.async.cg.shared.global [%0], [%1], 16;"
                 :: "r"(dst), "l"(src));
}
#define CP_COMMIT() asm volatile("cp.async.commit_group;")
#define CP_WAIT(n)  asm volatile("cp.async.wait_group %0;" :: "n"(n))

__device__ __forceinline__ uint32_t smem_u32(const void* p) {
    uint32_t a;
    asm("{ .reg .u64 t; cvta.to.shared.u64 t, %1; cvt.u32.u64 %0, t; }"
        : "=r"(a) : "l"(p));
    return a;
}

// ---------------------------------------------------------------------------
// Prep kernels: fp32 -> fp16
// ---------------------------------------------------------------------------
__global__ void to_half(const float* __restrict__ in, int n) {
    int i = (blockIdx.x * blockDim.x + threadIdx.x) * 4;
    if (i >= n) return;
    float4 v = *(const float4*)(in + i);
    __half2 h0 = __floats2half2_rn(v.x, v.y);
    __half2 h1 = __floats2half2_rn(v.z, v.w);
    *(uint2*)(g_X16 + i) = make_uint2(h2u(h0), h2u(h1));
}

// in: [CC][N] row-major fp32 -> out: [N][CC] fp16 (K-major)
__global__ void transpose_half(const float* __restrict__ in, int which) {
    __shared__ float tile[32][33];
    const int N = (which == 1) ? N_QKV : CC;
    __half* out = (which == 1) ? (__half*)g_W1t : (__half*)g_W2t;
    const int n0 = blockIdx.x * 32, k0 = blockIdx.y * 32;
    const int tx = threadIdx.x, ty = threadIdx.y;
    #pragma unroll
    for (int i = 0; i < 4; i++)
        tile[ty + 8*i][tx] = in[(size_t)(k0 + ty + 8*i) * N + n0 + tx];
    __syncthreads();
    #pragma unroll
    for (int i = 0; i < 4; i++)
        out[(size_t)(n0 + ty + 8*i) * CC + k0 + tx] =
            __float2half_rn(tile[tx][ty + 8*i]);
}

// ---------------------------------------------------------------------------
// FP16 GEMM (byte-identical to R11 — WIN, do not touch).
// ---------------------------------------------------------------------------
#define PAD   40
#define STG   4
#define TILEH (128*PAD)
#define TILEB (TILEH*2)
#define GEMM_SMEM (STG * 2 * TILEB)

template <int MODE>
__global__ __launch_bounds__(256, 2) void gemm16(const float* __restrict__ bias,
                                                 float* __restrict__ C) {
    extern __shared__ __half hsm[];
    __half* As = hsm;
    __half* Bs = hsm + STG * TILEH;

    const __half* A = (MODE == 0) ? (const __half*)g_X16 : (const __half*)g_O;
    const __half* B = (MODE == 0) ? (const __half*)g_W1t : (const __half*)g_W2t;

    const int tid  = threadIdx.x;
    const int lane = tid & 31;
    const int g    = lane >> 2;
    const int q    = lane & 3;
    const int wid  = tid >> 5;
    const int wm   = (wid & 3) * 32;
    const int wn   = (wid >> 2) * 64;

    const int bm = blockIdx.y * 128;
    const int bn = blockIdx.x * 128;

    const uint32_t sA = smem_u32(As);
    const uint32_t sB = smem_u32(Bs);

    const int lr = lane & 15;
    const int lc = (lane >> 4) * 8;

    const int frow = tid >> 1;
    const int fc   = (tid & 1) * 16;
    auto fill = [&](int s, int k0) {
        const __half* ap = A + (size_t)(bm + frow) * CC + k0 + fc;
        const __half* bp = B + (size_t)(bn + frow) * CC + k0 + fc;
        uint32_t da = sA + (uint32_t)(s * TILEH + frow * PAD + fc) * 2;
        uint32_t db = sB + (uint32_t)(s * TILEH + frow * PAD + fc) * 2;
        cp16(da, ap); cp16(da + 16, ap + 8);
        cp16(db, bp); cp16(db + 16, bp + 8);
    };

    float c[2][8][4];
    #pragma unroll
    for (int mt = 0; mt < 2; mt++)
        #pragma unroll
        for (int nt = 0; nt < 8; nt++)
            #pragma unroll
            for (int r = 0; r < 4; r++) c[mt][nt][r] = 0.0f;

    const int NT = CC / 32;
    fill(0, 0);  CP_COMMIT();
    fill(1, 32); CP_COMMIT();
    fill(2, 64); CP_COMMIT();

    for (int t = 0; t < NT; t++) {
        CP_WAIT(2);
        __syncthreads();

        const int tn = t + 3;
        if (tn < NT) fill(tn & (STG - 1), tn * 32);
        CP_COMMIT();

        const uint32_t aoff = sA + (uint32_t)(t & (STG - 1)) * TILEB;
        const uint32_t boff = sB + (uint32_t)(t & (STG - 1)) * TILEB;

        #pragma unroll
        for (int kw = 0; kw < 32; kw += 16) {
            uint32_t a[2][4];
            #pragma unroll
            for (int mt = 0; mt < 2; mt++)
                ldsm4(a[mt],
                      aoff + (uint32_t)((wm + mt * 16 + lr) * PAD + kw + lc) * 2);
            #pragma unroll
            for (int nt2 = 0; nt2 < 4; nt2++) {
                uint32_t b[4];
                ldsm4(b,
                      boff + (uint32_t)((wn + nt2 * 16 + lr) * PAD + kw + lc) * 2);
                mma16(c[0][2 * nt2],     a[0], b[0], b[2]);
                mma16(c[1][2 * nt2],     a[1], b[0], b[2]);
                mma16(c[0][2 * nt2 + 1], a[0], b[1], b[3]);
                mma16(c[1][2 * nt2 + 1], a[1], b[1], b[3]);
            }
        }
    }

    #pragma unroll
    for (int mt = 0; mt < 2; mt++) {
        #pragma unroll
        for (int nt = 0; nt < 8; nt++) {
            #pragma unroll
            for (int r = 0; r < 4; r++) {
                int row = bm + wm + mt * 16 + g + (r >> 1) * 8;
                int col = bn + wn + nt * 8 + q * 2 + (r & 1);
                float v = c[mt][nt][r] + bias[col];
                if (MODE == 0) {
                    int b  = row >> 11;
                    int tt = row & 2047;
                    int which = col >> 10;
                    int cc = col & 1023;
                    int h = cc >> 6;
                    int d = cc & 63;
                    size_t bh = (size_t)(b * NH + h);
                    if (which == 0)
                        g_Q[(bh * TT + tt) * HD + d] = __float2half_rn(v * 0.125f);
                    else if (which == 1)
                        g_K[(bh * TT + tt) * HD + d] = __float2half_rn(v);
                    else
                        g_Vt[(bh * HD + d) * TT + tt] = __float2half_rn(v);
                } else {
                    C[(size_t)row * CC + col] = v;
                }
            }
        }
    }
}

// ---------------------------------------------------------------------------
// Flash attention v2: ldmatrix fragments.
// 144 scalar LDS per tile per warp -> 36 ldmatrix.x4.
// ---------------------------------------------------------------------------
#define KPH 72
#define VPH 72
#define PPH 72
#define FLASH_SMEM ((2*64*KPH + 2*64*VPH + 128*PPH) * 2)

__global__ __launch_bounds__(256) void flash16() {
    extern __shared__ __half fsm[];
    __half* Ks = fsm;                         // [2][64*KPH]
    __half* Vs = fsm + 2 * 64 * KPH;          // [2][64*VPH]
    __half* Ps = fsm + 2 * 64 * KPH + 2 * 64 * VPH;  // [128*PPH]

    const int tid  = threadIdx.x;
    const int lane = tid & 31;
    const int g    = lane >> 2;
    const int q    = lane & 3;
    const int w    = tid >> 5;
    const int wrow = w * 16;

    const int qt = (int)(gridDim.x - 1) - (int)blockIdx.x;
    const int bh = blockIdx.y;
    const int nkv = 2 * qt + 2;

    // ldmatrix lane maps
    const int lrow8 = (lane & 7) | ((lane >> 1) & 8);  // B-frag row-within-16
    const int lk8   = (lane & 8);                      // B-frag k offset (halfs)
    const int arow  = (lane & 7) | (lane & 8);         // A-frag row-within-16
    const int akoff = (lane & 16) >> 1;                // A-frag k offset (halfs)

    const __half* Qp = g_Q + ((size_t)bh * TT + qt * 128) * HD;
    uint32_t qa[4][4];
    #pragma unroll
    for (int ks = 0; ks < 4; ks++) {
        const int r0 = wrow + g, r1 = r0 + 8;
        const int c0 = ks * 16 + 2 * q;
        qa[ks][0] = *(const uint32_t*)(Qp + r0 * HD + c0);
        qa[ks][1] = *(const uint32_t*)(Qp + r1 * HD + c0);
        qa[ks][2] = *(const uint32_t*)(Qp + r0 * HD + c0 + 8);
        qa[ks][3] = *(const uint32_t*)(Qp + r1 * HD + c0 + 8);
    }

    float o[8][4];
    #pragma unroll
    for (int nt = 0; nt < 8; nt++)
        #pragma unroll
        for (int r = 0; r < 4; r++) o[nt][r] = 0.0f;
    float m0 = -INFINITY, m1 = -INFINITY, l0 = 0.0f, l1 = 0.0f;

    const uint32_t sK = smem_u32(Ks);
    const uint32_t sV = smem_u32(Vs);
    const uint32_t sP = smem_u32(Ps);
    const int frow  = tid >> 2;
    const int fcolh = (tid & 3) * 16;

    auto fillkv = [&](int buf, int kti) {
        const __half* Kp = g_K + ((size_t)bh * TT + kti * 64 + frow) * HD + fcolh;
        const __half* Vp = g_Vt + ((size_t)bh * HD + frow) * TT + kti * 64 + fcolh;
        uint32_t dk = sK + (uint32_t)(buf * 64 * KPH + frow * KPH + fcolh) * 2;
        uint32_t dv = sV + (uint32_t)(buf * 64 * VPH + frow * VPH + fcolh) * 2;
        cp16(dk,      Kp);
        cp16(dk + 16, Kp + 8);
        cp16(dv,      Vp);
        cp16(dv + 16, Vp + 8);
    };

    fillkv(0, 0); CP_COMMIT();

    for (int ktt = 0; ktt < nkv; ktt++) {
        if (ktt + 1 < nkv) fillkv((ktt + 1) & 1, ktt + 1);
        CP_COMMIT();
        CP_WAIT(1);
        __syncthreads();

        const bool full_skip = (ktt * 64) > (qt * 128 + wrow + 15);
        if (!full_skip) {
            const uint32_t kbase = sK + (uint32_t)((ktt & 1) * 64 * KPH) * 2;
            const uint32_t vbase = sV + (uint32_t)((ktt & 1) * 64 * VPH) * 2;

            // S = Q K^T  — B-frags via ldmatrix.x4 (2 key-octets per load)
            float s[8][4];
            #pragma unroll
            for (int nt = 0; nt < 8; nt++)
                #pragma unroll
                for (int r = 0; r < 4; r++) s[nt][r] = 0.0f;

            #pragma unroll
            for (int ks = 0; ks < 4; ks++) {
                #pragma unroll
                for (int nt2 = 0; nt2 < 4; nt2++) {
                    uint32_t b[4];
                    ldsm4(b, kbase +
                          (uint32_t)((nt2 * 16 + lrow8) * KPH + ks * 16 + lk8) * 2);
                    mma16(s[2 * nt2],     qa[ks], b[0], b[1]);
                    mma16(s[2 * nt2 + 1], qa[ks], b[2], b[3]);
                }
            }

            // causal mask (global indices)
            const int rowg0 = qt * 128 + wrow + g;
            const int rowg1 = rowg0 + 8;
            if (ktt * 64 + 63 > qt * 128 + wrow) {
                #pragma unroll
                for (int nt = 0; nt < 8; nt++) {
                    const int c0 = ktt * 64 + nt * 8 + 2 * q;
                    if (c0     > rowg0) s[nt][0] = -INFINITY;
                    if (c0 + 1 > rowg0) s[nt][1] = -INFINITY;
                    if (c0     > rowg1) s[nt][2] = -INFINITY;
                    if (c0 + 1 > rowg1) s[nt][3] = -INFINITY;
                }
            }

            // online softmax (quad reduction)
            float mx0 = -INFINITY, mx1 = -INFINITY;
            #pragma unroll
            for (int nt = 0; nt < 8; nt++) {
                mx0 = fmaxf(mx0, fmaxf(s[nt][0], s[nt][1]));
                mx1 = fmaxf(mx1, fmaxf(s[nt][2], s[nt][3]));
            }
            mx0 = fmaxf(mx0, __shfl_xor_sync(0xffffffffu, mx0, 1));
            mx0 = fmaxf(mx0, __shfl_xor_sync(0xffffffffu, mx0, 2));
            mx1 = fmaxf(mx1, __shfl_xor_sync(0xffffffffu, mx1, 1));
            mx1 = fmaxf(mx1, __shfl_xor_sync(0xffffffffu, mx1, 2));

            float mn0 = fmaxf(m0, mx0), mn1 = fmaxf(m1, mx1);
            float corr0 = __expf(m0 - mn0), corr1 = __expf(m1 - mn1);
            m0 = mn0; m1 = mn1;

            float rs0 = 0.0f, rs1 = 0.0f;
            #pragma unroll
            for (int nt = 0; nt < 8; nt++) {
                s[nt][0] = __expf(s[nt][0] - m0); rs0 += s[nt][0];
                s[nt][1] = __expf(s[nt][1] - m0); rs0 += s[nt][1];
                s[nt][2] = __expf(s[nt][2] - m1); rs1 += s[nt][2];
                s[nt][3] = __expf(s[nt][3] - m1); rs1 += s[nt][3];
            }
            rs0 += __shfl_xor_sync(0xffffffffu, rs0, 1);
            rs0 += __shfl_xor_sync(0xffffffffu, rs0, 2);
            rs1 += __shfl_xor_sync(0xffffffffu, rs1, 1);
            rs1 += __shfl_xor_sync(0xffffffffu, rs1, 2);
            l0 = l0 * corr0 + rs0;
            l1 = l1 * corr1 + rs1;

            #pragma unroll
            for (int nt = 0; nt < 8; nt++) {
                o[nt][0] *= corr0; o[nt][1] *= corr0;
                o[nt][2] *= corr1; o[nt][3] *= corr1;
            }

            // P -> smem fp16 (own warp rows)
            uint32_t* Pu = (uint32_t*)Ps;
            #pragma unroll
            for (int nt = 0; nt < 8; nt++) {
                const int cw = (nt * 8 + 2 * q) >> 1;
                __half2 p0 = __floats2half2_rn(s[nt][0], s[nt][1]);
                __half2 p1 = __floats2half2_rn(s[nt][2], s[nt][3]);
                Pu[(wrow + g)     * 36 + cw] = h2u(p0);
                Pu[(wrow + g + 8) * 36 + cw] = h2u(p1);
            }
            __syncwarp();   // cross-lane P visibility before ldmatrix

            // O += P V — A-frags from P and B-frags from V^T via ldmatrix.x4
            #pragma unroll
            for (int kk = 0; kk < 4; kk++) {
                uint32_t a[4];
                ldsm4(a, sP +
                      (uint32_t)((wrow + arow) * PPH + kk * 16 + akoff) * 2);
                #pragma unroll
                for (int nt2 = 0; nt2 < 4; nt2++) {
                    uint32_t b[4];
                    ldsm4(b, vbase +
                          (uint32_t)((nt2 * 16 + lrow8) * VPH + kk * 16 + lk8) * 2);
                    mma16(o[2 * nt2],     a, b[0], b[1]);
                    mma16(o[2 * nt2 + 1], a, b[2], b[3]);
                }
            }
        }
        __syncthreads();
    }

    const float inv0 = 1.0f / l0, inv1 = 1.0f / l1;
    const int b = bh >> 4;
    const int h = bh & 15;
    __half* obase = g_O + ((size_t)b * TT + qt * 128) * CC + h * HD;
    const int r0 = wrow + g, r1 = r0 + 8;
    #pragma unroll
    for (int nt = 0; nt < 8; nt++) {
        const int col = nt * 8 + 2 * q;
        __half2 v0 = __floats2half2_rn(o[nt][0] * inv0, o[nt][1] * inv0);
        __half2 v1 = __floats2half2_rn(o[nt][2] * inv1, o[nt][3] * inv1);
        *(__half2*)(obase + (size_t)r0 * CC + col) = v0;
        *(__half2*)(obase + (size_t)r1 * CC + col) = v1;
    }
}

// ---------------------------------------------------------------------------
extern "C" void kernel_launch(void* const* d_in, const int* in_sizes, int n_in,
                              void* d_out, int out_size) {
    const float* x     = (const float*)d_in[0];
    const float* W_qkv = (const float*)d_in[1];
    const float* b_qkv = (const float*)d_in[2];
    const float* W_out = (const float*)d_in[3];
    const float* b_out = (const float*)d_in[4];
    float* out = (float*)d_out;

    cudaFuncSetAttribute(flash16,
                         cudaFuncAttributeMaxDynamicSharedMemorySize,
                         FLASH_SMEM);
    cudaFuncSetAttribute(gemm16<0>,
                         cudaFuncAttributeMaxDynamicSharedMemorySize,
                         GEMM_SMEM);
    cudaFuncSetAttribute(gemm16<1>,
                         cudaFuncAttributeMaxDynamicSharedMemorySize,
                         GEMM_SMEM);

    to_half<<<(MM * CC / 4 + 255) / 256, 256>>>(x, MM * CC);
    dim3 gT1(N_QKV / 32, CC / 32);
    transpose_half<<<gT1, dim3(32, 8)>>>(W_qkv, 1);
    dim3 gT2(CC / 32, CC / 32);
    transpose_half<<<gT2, dim3(32, 8)>>>(W_out, 2);

    dim3 gQKV(N_QKV / 128, MM / 128);      // 24 x 64
    gemm16<0><<<gQKV, 256, GEMM_SMEM>>>(b_qkv, nullptr);

    dim3 gFA(TT / 128, BB * NH);           // 16 x 64
    flash16<<<gFA, 256, FLASH_SMEM>>>();

    dim3 gOUT(CC / 128, MM / 128);         // 8 x 64
    gemm16<1><<<gOUT, 256, GEMM_SMEM>>>(b_out, out);
}

// round 14
// speedup vs baseline: 1.1226x; 1.1226x over previous
#include <cuda_runtime.h>
#include <cuda_fp16.h>
#include <math.h>
#include <stdint.h>

// Shapes (fixed by the problem)
#define BB   4
#define TT   2048
#define CC   1024
#define NH   16
#define HD   64
#define MM   (BB*TT)          // 8192
#define N_QKV (3*CC)          // 3072

// ---------------------------------------------------------------------------
// Scratch (device globals; no allocation allowed). All fp16 operands.
// ---------------------------------------------------------------------------
__device__ __half g_Q [BB*NH*TT*HD];   // (B,H,T,D), Q pre-scaled by 1/8
__device__ __half g_K [BB*NH*TT*HD];   // (B,H,T,D)
__device__ __half g_Vt[BB*NH*HD*TT];   // (B,H,D,T)  V TRANSPOSED
__device__ __half g_O [MM*CC];         // (B,T,C) attention out
__device__ __half g_X16[MM*CC];        // fp16 x
__device__ __half g_W1t[N_QKV*CC];     // W_qkv^T [3072][1024]
__device__ __half g_W2t[CC*CC];        // W_out^T [1024][1024]

// ---------------------------------------------------------------------------
// Helpers
// ---------------------------------------------------------------------------
__device__ __forceinline__ uint32_t h2u(__half2 h) {
    uint32_t u;
    *(__half2*)&u = h;
    return u;
}

__device__ __forceinline__ void mma16(float c[4], const uint32_t a[4],
                                      uint32_t b0, uint32_t b1) {
    asm volatile(
        "mma.sync.aligned.m16n8k16.row.col.f32.f16.f16.f32 "
        "{%0,%1,%2,%3},{%4,%5,%6,%7},{%8,%9},{%0,%1,%2,%3};"
        : "+f"(c[0]), "+f"(c[1]), "+f"(c[2]), "+f"(c[3])
        : "r"(a[0]), "r"(a[1]), "r"(a[2]), "r"(a[3]), "r"(b0), "r"(b1));
}

__device__ __forceinline__ void ldsm4(uint32_t r[4], uint32_t addr) {
    asm volatile(
        "ldmatrix.sync.aligned.m8n8.x4.shared.b16 {%0,%1,%2,%3}, [%4];"
        : "=r"(r[0]), "=r"(r[1]), "=r"(r[2]), "=r"(r[3]) : "r"(addr));
}

__device__ __forceinline__ void cp16(uint32_t dst, const void* src) {
    asm volatile("cp.async.cg.shared.global [%0], [%1], 16;"
                 :: "r"(dst), "l"(src));
}
#define CP_COMMIT() asm volatile("cp.async.commit_group;")
#define CP_WAIT(n)  asm volatile("cp.async.wait_group %0;" :: "n"(n))

__device__ __forceinline__ uint32_t smem_u32(const void* p) {
    uint32_t a;
    asm("{ .reg .u64 t; cvta.to.shared.u64 t, %1; cvt.u32.u64 %0, t; }"
        : "=r"(a) : "l"(p));
    return a;
}

// ---------------------------------------------------------------------------
// Prep kernels: fp32 -> fp16
// ---------------------------------------------------------------------------
__global__ void to_half(const float* __restrict__ in, int n) {
    int i = (blockIdx.x * blockDim.x + threadIdx.x) * 4;
    if (i >= n) return;
    float4 v = *(const float4*)(in + i);
    __half2 h0 = __floats2half2_rn(v.x, v.y);
    __half2 h1 = __floats2half2_rn(v.z, v.w);
    *(uint2*)(g_X16 + i) = make_uint2(h2u(h0), h2u(h1));
}

// in: [CC][N] row-major fp32 -> out: [N][CC] fp16 (K-major)
__global__ void transpose_half(const float* __restrict__ in, int which) {
    __shared__ float tile[32][33];
    const int N = (which == 1) ? N_QKV : CC;
    __half* out = (which == 1) ? (__half*)g_W1t : (__half*)g_W2t;
    const int n0 = blockIdx.x * 32, k0 = blockIdx.y * 32;
    const int tx = threadIdx.x, ty = threadIdx.y;
    #pragma unroll
    for (int i = 0; i < 4; i++)
        tile[ty + 8*i][tx] = in[(size_t)(k0 + ty + 8*i) * N + n0 + tx];
    __syncthreads();
    #pragma unroll
    for (int i = 0; i < 4; i++)
        out[(size_t)(n0 + ty + 8*i) * CC + k0 + tx] =
            __float2half_rn(tile[tx][ty + 8*i]);
}

// ---------------------------------------------------------------------------
// FP16 GEMM v4 (R14): 512 threads, 16 warps (4x4), warp tile 32x32.
// 8 warps/SMSP for latency hiding; 32 acc regs/thread fits (512,2) cap.
// STG=4, BK=32 halfs, PAD=40 — smem layout identical to R11.
// ---------------------------------------------------------------------------
#define PAD   40
#define STG   4
#define TILEH (128*PAD)
#define TILEB (TILEH*2)
#define GEMM_SMEM (STG * 2 * TILEB)

template <int MODE>
__global__ __launch_bounds__(512, 2) void gemm16(const float* __restrict__ bias,
                                                 float* __restrict__ C) {
    extern __shared__ __half hsm[];
    __half* As = hsm;
    __half* Bs = hsm + STG * TILEH;

    const __half* A = (MODE == 0) ? (const __half*)g_X16 : (const __half*)g_O;
    const __half* B = (MODE == 0) ? (const __half*)g_W1t : (const __half*)g_W2t;

    const int tid  = threadIdx.x;
    const int lane = tid & 31;
    const int g    = lane >> 2;
    const int q    = lane & 3;
    const int wid  = tid >> 5;          // 0..15
    const int wm   = (wid & 3) * 32;    // 4 warp-rows
    const int wn   = (wid >> 2) * 32;   // 4 warp-cols

    const int bm = blockIdx.y * 128;
    const int bn = blockIdx.x * 128;

    const uint32_t sA = smem_u32(As);
    const uint32_t sB = smem_u32(Bs);

    const int lr = lane & 15;
    const int lc = (lane >> 4) * 8;

    // fill: 512 threads, 1 cp16 for A + 1 for B each
    const int frow = tid >> 2;          // 0..127
    const int fc   = (tid & 3) * 8;     // 0,8,16,24 halfs
    auto fill = [&](int s, int k0) {
        const __half* ap = A + (size_t)(bm + frow) * CC + k0 + fc;
        const __half* bp = B + (size_t)(bn + frow) * CC + k0 + fc;
        cp16(sA + (uint32_t)(s * TILEH + frow * PAD + fc) * 2, ap);
        cp16(sB + (uint32_t)(s * TILEH + frow * PAD + fc) * 2, bp);
    };

    float c[2][4][4];
    #pragma unroll
    for (int mt = 0; mt < 2; mt++)
        #pragma unroll
        for (int nt = 0; nt < 4; nt++)
            #pragma unroll
            for (int r = 0; r < 4; r++) c[mt][nt][r] = 0.0f;

    const int NT = CC / 32;   // 32 stages
    fill(0, 0);  CP_COMMIT();
    fill(1, 32); CP_COMMIT();
    fill(2, 64); CP_COMMIT();

    for (int t = 0; t < NT; t++) {
        CP_WAIT(2);
        __syncthreads();

        const int tn = t + 3;
        if (tn < NT) fill(tn & (STG - 1), tn * 32);
        CP_COMMIT();

        const uint32_t aoff = sA + (uint32_t)(t & (STG - 1)) * TILEB;
        const uint32_t boff = sB + (uint32_t)(t & (STG - 1)) * TILEB;

        #pragma unroll
        for (int kw = 0; kw < 32; kw += 16) {
            uint32_t a[2][4];
            #pragma unroll
            for (int mt = 0; mt < 2; mt++)
                ldsm4(a[mt],
                      aoff + (uint32_t)((wm + mt * 16 + lr) * PAD + kw + lc) * 2);
            #pragma unroll
            for (int nt2 = 0; nt2 < 2; nt2++) {
                uint32_t b[4];
                ldsm4(b,
                      boff + (uint32_t)((wn + nt2 * 16 + lr) * PAD + kw + lc) * 2);
                mma16(c[0][2 * nt2],     a[0], b[0], b[2]);
                mma16(c[1][2 * nt2],     a[1], b[0], b[2]);
                mma16(c[0][2 * nt2 + 1], a[0], b[1], b[3]);
                mma16(c[1][2 * nt2 + 1], a[1], b[1], b[3]);
            }
        }
    }

    // epilogue
    #pragma unroll
    for (int mt = 0; mt < 2; mt++) {
        #pragma unroll
        for (int nt = 0; nt < 4; nt++) {
            #pragma unroll
            for (int r = 0; r < 4; r++) {
                int row = bm + wm + mt * 16 + g + (r >> 1) * 8;
                int col = bn + wn + nt * 8 + q * 2 + (r & 1);
                float v = c[mt][nt][r] + bias[col];
                if (MODE == 0) {
                    int b  = row >> 11;
                    int tt = row & 2047;
                    int which = col >> 10;
                    int cc = col & 1023;
                    int h = cc >> 6;
                    int d = cc & 63;
                    size_t bh = (size_t)(b * NH + h);
                    if (which == 0)
                        g_Q[(bh * TT + tt) * HD + d] = __float2half_rn(v * 0.125f);
                    else if (which == 1)
                        g_K[(bh * TT + tt) * HD + d] = __float2half_rn(v);
                    else
                        g_Vt[(bh * HD + d) * TT + tt] = __float2half_rn(v);
                } else {
                    C[(size_t)row * CC + col] = v;
                }
            }
        }
    }
}

// ---------------------------------------------------------------------------
// Flash attention — REVERTED to R11 scalar-LDS version (proven best: 553.1).
// ---------------------------------------------------------------------------
#define KPH 72
#define VPH 72
#define PPH 72
#define FLASH_SMEM ((2*64*KPH + 2*64*VPH + 128*PPH) * 2)

__global__ __launch_bounds__(256) void flash16() {
    extern __shared__ __half fsm[];
    __half* Ks = fsm;                         // [2][64*KPH]
    __half* Vs = fsm + 2 * 64 * KPH;          // [2][64*VPH]
    __half* Ps = fsm + 2 * 64 * KPH + 2 * 64 * VPH;  // [128*PPH]

    const int tid  = threadIdx.x;
    const int lane = tid & 31;
    const int g    = lane >> 2;
    const int q    = lane & 3;
    const int w    = tid >> 5;
    const int wrow = w * 16;

    const int qt = (int)(gridDim.x - 1) - (int)blockIdx.x;
    const int bh = blockIdx.y;
    const int nkv = 2 * qt + 2;

    const __half* Qp = g_Q + ((size_t)bh * TT + qt * 128) * HD;
    uint32_t qa[4][4];
    #pragma unroll
    for (int ks = 0; ks < 4; ks++) {
        const int r0 = wrow + g, r1 = r0 + 8;
        const int c0 = ks * 16 + 2 * q;
        qa[ks][0] = *(const uint32_t*)(Qp + r0 * HD + c0);
        qa[ks][1] = *(const uint32_t*)(Qp + r1 * HD + c0);
        qa[ks][2] = *(const uint32_t*)(Qp + r0 * HD + c0 + 8);
        qa[ks][3] = *(const uint32_t*)(Qp + r1 * HD + c0 + 8);
    }

    float o[8][4];
    #pragma unroll
    for (int nt = 0; nt < 8; nt++)
        #pragma unroll
        for (int r = 0; r < 4; r++) o[nt][r] = 0.0f;
    float m0 = -INFINITY, m1 = -INFINITY, l0 = 0.0f, l1 = 0.0f;

    const uint32_t sK = smem_u32(Ks);
    const uint32_t sV = smem_u32(Vs);
    const int frow  = tid >> 2;
    const int fcolh = (tid & 3) * 16;

    auto fillkv = [&](int buf, int kti) {
        const __half* Kp = g_K + ((size_t)bh * TT + kti * 64 + frow) * HD + fcolh;
        const __half* Vp = g_Vt + ((size_t)bh * HD + frow) * TT + kti * 64 + fcolh;
        uint32_t dk = sK + (uint32_t)(buf * 64 * KPH + frow * KPH + fcolh) * 2;
        uint32_t dv = sV + (uint32_t)(buf * 64 * VPH + frow * VPH + fcolh) * 2;
        cp16(dk,      Kp);
        cp16(dk + 16, Kp + 8);
        cp16(dv,      Vp);
        cp16(dv + 16, Vp + 8);
    };

    fillkv(0, 0); CP_COMMIT();

    for (int ktt = 0; ktt < nkv; ktt++) {
        if (ktt + 1 < nkv) fillkv((ktt + 1) & 1, ktt + 1);
        CP_COMMIT();
        CP_WAIT(1);
        __syncthreads();

        const bool full_skip = (ktt * 64) > (qt * 128 + wrow + 15);
        if (!full_skip) {
            const uint32_t* Kb = (const uint32_t*)(Ks + (ktt & 1) * 64 * KPH);
            const uint32_t* Vb = (const uint32_t*)(Vs + (ktt & 1) * 64 * VPH);

            float s[8][4];
            #pragma unroll
            for (int nt = 0; nt < 8; nt++)
                #pragma unroll
                for (int r = 0; r < 4; r++) s[nt][r] = 0.0f;

            #pragma unroll
            for (int ks = 0; ks < 4; ks++) {
                #pragma unroll
                for (int nt = 0; nt < 8; nt++) {
                    uint32_t b0 = Kb[(nt * 8 + g) * 36 + ks * 8 + q];
                    uint32_t b1 = Kb[(nt * 8 + g) * 36 + ks * 8 + q + 4];
                    mma16(s[nt], qa[ks], b0, b1);
                }
            }

            const int rowg0 = qt * 128 + wrow + g;
            const int rowg1 = rowg0 + 8;
            if (ktt * 64 + 63 > qt * 128 + wrow) {
                #pragma unroll
                for (int nt = 0; nt < 8; nt++) {
                    const int c0 = ktt * 64 + nt * 8 + 2 * q;
                    if (c0     > rowg0) s[nt][0] = -INFINITY;
                    if (c0 + 1 > rowg0) s[nt][1] = -INFINITY;
                    if (c0     > rowg1) s[nt][2] = -INFINITY;
                    if (c0 + 1 > rowg1) s[nt][3] = -INFINITY;
                }
            }

            float mx0 = -INFINITY, mx1 = -INFINITY;
            #pragma unroll
            for (int nt = 0; nt < 8; nt++) {
                mx0 = fmaxf(mx0, fmaxf(s[nt][0], s[nt][1]));
                mx1 = fmaxf(mx1, fmaxf(s[nt][2], s[nt][3]));
            }
            mx0 = fmaxf(mx0, __shfl_xor_sync(0xffffffffu, mx0, 1));
            mx0 = fmaxf(mx0, __shfl_xor_sync(0xffffffffu, mx0, 2));
            mx1 = fmaxf(mx1, __shfl_xor_sync(0xffffffffu, mx1, 1));
            mx1 = fmaxf(mx1, __shfl_xor_sync(0xffffffffu, mx1, 2));

            float mn0 = fmaxf(m0, mx0), mn1 = fmaxf(m1, mx1);
            float corr0 = __expf(m0 - mn0), corr1 = __expf(m1 - mn1);
            m0 = mn0; m1 = mn1;

            float rs0 = 0.0f, rs1 = 0.0f;
            #pragma unroll
            for (int nt = 0; nt < 8; nt++) {
                s[nt][0] = __expf(s[nt][0] - m0); rs0 += s[nt][0];
                s[nt][1] = __expf(s[nt][1] - m0); rs0 += s[nt][1];
                s[nt][2] = __expf(s[nt][2] - m1); rs1 += s[nt][2];
                s[nt][3] = __expf(s[nt][3] - m1); rs1 += s[nt][3];
            }
            rs0 += __shfl_xor_sync(0xffffffffu, rs0, 1);
            rs0 += __shfl_xor_sync(0xffffffffu, rs0, 2);
            rs1 += __shfl_xor_sync(0xffffffffu, rs1, 1);
            rs1 += __shfl_xor_sync(0xffffffffu, rs1, 2);
            l0 = l0 * corr0 + rs0;
            l1 = l1 * corr1 + rs1;

            #pragma unroll
            for (int nt = 0; nt < 8; nt++) {
                o[nt][0] *= corr0; o[nt][1] *= corr0;
                o[nt][2] *= corr1; o[nt][3] *= corr1;
            }

            uint32_t* Pu = (uint32_t*)Ps;
            #pragma unroll
            for (int nt = 0; nt < 8; nt++) {
                const int cw = (nt * 8 + 2 * q) >> 1;
                __half2 p0 = __floats2half2_rn(s[nt][0], s[nt][1]);
                __half2 p1 = __floats2half2_rn(s[nt][2], s[nt][3]);
                Pu[(wrow + g)     * 36 + cw] = h2u(p0);
                Pu[(wrow + g + 8) * 36 + cw] = h2u(p1);
            }

            #pragma unroll
            for (int kk = 0; kk < 4; kk++) {
                uint32_t a[4];
                a[0] = Pu[(wrow + g)     * 36 + kk * 8 + q];
                a[1] = Pu[(wrow + g + 8) * 36 + kk * 8 + q];
                a[2] = Pu[(wrow + g)     * 36 + kk * 8 + q + 4];
                a[3] = Pu[(wrow + g + 8) * 36 + kk * 8 + q + 4];
                #pragma unroll
                for (int nt = 0; nt < 8; nt++) {
                    uint32_t b0 = Vb[(nt * 8 + g) * 36 + kk * 8 + q];
                    uint32_t b1 = Vb[(nt * 8 + g) * 36 + kk * 8 + q + 4];
                    mma16(o[nt], a, b0, b1);
                }
            }
        }
        __syncthreads();
    }

    const float inv0 = 1.0f / l0, inv1 = 1.0f / l1;
    const int b = bh >> 4;
    const int h = bh & 15;
    __half* obase = g_O + ((size_t)b * TT + qt * 128) * CC + h * HD;
    const int r0 = wrow + g, r1 = r0 + 8;
    #pragma unroll
    for (int nt = 0; nt < 8; nt++) {
        const int col = nt * 8 + 2 * q;
        __half2 v0 = __floats2half2_rn(o[nt][0] * inv0, o[nt][1] * inv0);
        __half2 v1 = __floats2half2_rn(o[nt][2] * inv1, o[nt][3] * inv1);
        *(__half2*)(obase + (size_t)r0 * CC + col) = v0;
        *(__half2*)(obase + (size_t)r1 * CC + col) = v1;
    }
}

// ---------------------------------------------------------------------------
extern "C" void kernel_launch(void* const* d_in, const int* in_sizes, int n_in,
                              void* d_out, int out_size) {
    const float* x     = (const float*)d_in[0];
    const float* W_qkv = (const float*)d_in[1];
    const float* b_qkv = (const float*)d_in[2];
    const float* W_out = (const float*)d_in[3];
    const float* b_out = (const float*)d_in[4];
    float* out = (float*)d_out;

    cudaFuncSetAttribute(flash16,
                         cudaFuncAttributeMaxDynamicSharedMemorySize,
                         FLASH_SMEM);
    cudaFuncSetAttribute(gemm16<0>,
                         cudaFuncAttributeMaxDynamicSharedMemorySize,
                         GEMM_SMEM);
    cudaFuncSetAttribute(gemm16<1>,
                         cudaFuncAttributeMaxDynamicSharedMemorySize,
                         GEMM_SMEM);

    to_half<<<(MM * CC / 4 + 255) / 256, 256>>>(x, MM * CC);
    dim3 gT1(N_QKV / 32, CC / 32);
    transpose_half<<<gT1, dim3(32, 8)>>>(W_qkv, 1);
    dim3 gT2(CC / 32, CC / 32);
    transpose_half<<<gT2, dim3(32, 8)>>>(W_out, 2);

    dim3 gQKV(N_QKV / 128, MM / 128);      // 24 x 64
    gemm16<0><<<gQKV, 512, GEMM_SMEM>>>(b_qkv, nullptr);

    dim3 gFA(TT / 128, BB * NH);           // 16 x 64
    flash16<<<gFA, 256, FLASH_SMEM>>>();

    dim3 gOUT(CC / 128, MM / 128);         // 8 x 64
    gemm16<1><<<gOUT, 512, GEMM_SMEM>>>(b_out, out);
}

// round 15
// speedup vs baseline: 1.2035x; 1.0720x over previous
#include <cuda_runtime.h>
#include <cuda_fp16.h>
#include <math.h>
#include <stdint.h>

// Shapes (fixed by the problem)
#define BB   4
#define TT   2048
#define CC   1024
#define NH   16
#define HD   64
#define MM   (BB*TT)          // 8192
#define N_QKV (3*CC)          // 3072

// ---------------------------------------------------------------------------
// Scratch (device globals; no allocation allowed). All fp16 operands.
// ---------------------------------------------------------------------------
__device__ __half g_Q [BB*NH*TT*HD];   // (B,H,T,D), Q pre-scaled by 1/8
__device__ __half g_K [BB*NH*TT*HD];   // (B,H,T,D)
__device__ __half g_Vt[BB*NH*HD*TT];   // (B,H,D,T)  V TRANSPOSED
__device__ __half g_O [MM*CC];         // (B,T,C) attention out
__device__ __half g_X16[MM*CC];        // fp16 x
__device__ __half g_W1t[N_QKV*CC];     // W_qkv^T [3072][1024]
__device__ __half g_W2t[CC*CC];        // W_out^T [1024][1024]

// ---------------------------------------------------------------------------
// Helpers
// ---------------------------------------------------------------------------
__device__ __forceinline__ uint32_t h2u(__half2 h) {
    uint32_t u;
    *(__half2*)&u = h;
    return u;
}

__device__ __forceinline__ void mma16(float c[4], const uint32_t a[4],
                                      uint32_t b0, uint32_t b1) {
    asm volatile(
        "mma.sync.aligned.m16n8k16.row.col.f32.f16.f16.f32 "
        "{%0,%1,%2,%3},{%4,%5,%6,%7},{%8,%9},{%0,%1,%2,%3};"
        : "+f"(c[0]), "+f"(c[1]), "+f"(c[2]), "+f"(c[3])
        : "r"(a[0]), "r"(a[1]), "r"(a[2]), "r"(a[3]), "r"(b0), "r"(b1));
}

__device__ __forceinline__ void ldsm4(uint32_t r[4], uint32_t addr) {
    asm volatile(
        "ldmatrix.sync.aligned.m8n8.x4.shared.b16 {%0,%1,%2,%3}, [%4];"
        : "=r"(r[0]), "=r"(r[1]), "=r"(r[2]), "=r"(r[3]) : "r"(addr));
}

__device__ __forceinline__ void cp16(uint32_t dst, const void* src) {
    asm volatile("cp.async.cg.shared.global [%0], [%1], 16;"
                 :: "r"(dst), "l"(src));
}
#define CP_COMMIT() asm volatile("cp.async.commit_group;")
#define CP_WAIT(n)  asm volatile("cp.async.wait_group %0;" :: "n"(n))

__device__ __forceinline__ uint32_t smem_u32(const void* p) {
    uint32_t a;
    asm("{ .reg .u64 t; cvta.to.shared.u64 t, %1; cvt.u32.u64 %0, t; }"
        : "=r"(a) : "l"(p));
    return a;
}

// ---------------------------------------------------------------------------
// Merged prep kernel (R15): one launch does x->fp16 + both W transposes.
// blocks [0, 8192)          : to_half of x (256 thr x 4 elems)
// blocks [8192, 8192+3072)  : W_qkv transpose (32x32 tile per block)
// blocks [11264, 11264+1024): W_out transpose
// ---------------------------------------------------------------------------
#define PREP_X_BLOCKS  (MM * CC / 1024)          // 8192
#define PREP_W1_BLOCKS ((N_QKV / 32) * (CC / 32))// 3072
#define PREP_W2_BLOCKS ((CC / 32) * (CC / 32))   // 1024
#define PREP_BLOCKS (PREP_X_BLOCKS + PREP_W1_BLOCKS + PREP_W2_BLOCKS)

__global__ void prep(const float* __restrict__ x,
                     const float* __restrict__ W1,
                     const float* __restrict__ W2) {
    __shared__ float tile[32][33];
    const int bid = blockIdx.x;
    const int tid = threadIdx.x;

    if (bid < PREP_X_BLOCKS) {
        int i = (bid * 256 + tid) * 4;
        float4 v = *(const float4*)(x + i);
        __half2 h0 = __floats2half2_rn(v.x, v.y);
        __half2 h1 = __floats2half2_rn(v.z, v.w);
        *(uint2*)(g_X16 + i) = make_uint2(h2u(h0), h2u(h1));
        return;
    }

    // transpose path: [CC][N] fp32 -> [N][CC] fp16
    const float* in;
    __half* out;
    int N, tb;
    if (bid < PREP_X_BLOCKS + PREP_W1_BLOCKS) {
        in = W1; out = g_W1t; N = N_QKV; tb = bid - PREP_X_BLOCKS;
    } else {
        in = W2; out = g_W2t; N = CC; tb = bid - PREP_X_BLOCKS - PREP_W1_BLOCKS;
    }
    const int nblk = N / 32;
    const int n0 = (tb % nblk) * 32;
    const int k0 = (tb / nblk) * 32;
    const int tx = tid & 31, ty = tid >> 5;   // 32 x 8
    #pragma unroll
    for (int i = 0; i < 4; i++)
        tile[ty + 8*i][tx] = in[(size_t)(k0 + ty + 8*i) * N + n0 + tx];
    __syncthreads();
    #pragma unroll
    for (int i = 0; i < 4; i++)
        out[(size_t)(n0 + ty + 8*i) * CC + k0 + tx] =
            __float2half_rn(tile[tx][ty + 8*i]);
}

// ---------------------------------------------------------------------------
// FP16 GEMM (mainloop byte-identical to R14; epilogue vectorized in R15).
// 512 threads, 16 warps (4x4), warp tile 32x32, STG=4, BK=32, PAD=40.
// ---------------------------------------------------------------------------
#define PAD   40
#define STG   4
#define TILEH (128*PAD)
#define TILEB (TILEH*2)
#define GEMM_SMEM (STG * 2 * TILEB)

template <int MODE>
__global__ __launch_bounds__(512, 2) void gemm16(const float* __restrict__ bias,
                                                 float* __restrict__ C) {
    extern __shared__ __half hsm[];
    __half* As = hsm;
    __half* Bs = hsm + STG * TILEH;

    const __half* A = (MODE == 0) ? (const __half*)g_X16 : (const __half*)g_O;
    const __half* B = (MODE == 0) ? (const __half*)g_W1t : (const __half*)g_W2t;

    const int tid  = threadIdx.x;
    const int lane = tid & 31;
    const int g    = lane >> 2;
    const int q    = lane & 3;
    const int wid  = tid >> 5;
    const int wm   = (wid & 3) * 32;
    const int wn   = (wid >> 2) * 32;

    const int bm = blockIdx.y * 128;
    const int bn = blockIdx.x * 128;

    const uint32_t sA = smem_u32(As);
    const uint32_t sB = smem_u32(Bs);

    const int lr = lane & 15;
    const int lc = (lane >> 4) * 8;

    const int frow = tid >> 2;
    const int fc   = (tid & 3) * 8;
    auto fill = [&](int s, int k0) {
        const __half* ap = A + (size_t)(bm + frow) * CC + k0 + fc;
        const __half* bp = B + (size_t)(bn + frow) * CC + k0 + fc;
        cp16(sA + (uint32_t)(s * TILEH + frow * PAD + fc) * 2, ap);
        cp16(sB + (uint32_t)(s * TILEH + frow * PAD + fc) * 2, bp);
    };

    float c[2][4][4];
    #pragma unroll
    for (int mt = 0; mt < 2; mt++)
        #pragma unroll
        for (int nt = 0; nt < 4; nt++)
            #pragma unroll
            for (int r = 0; r < 4; r++) c[mt][nt][r] = 0.0f;

    const int NT = CC / 32;
    fill(0, 0);  CP_COMMIT();
    fill(1, 32); CP_COMMIT();
    fill(2, 64); CP_COMMIT();

    for (int t = 0; t < NT; t++) {
        CP_WAIT(2);
        __syncthreads();

        const int tn = t + 3;
        if (tn < NT) fill(tn & (STG - 1), tn * 32);
        CP_COMMIT();

        const uint32_t aoff = sA + (uint32_t)(t & (STG - 1)) * TILEB;
        const uint32_t boff = sB + (uint32_t)(t & (STG - 1)) * TILEB;

        #pragma unroll
        for (int kw = 0; kw < 32; kw += 16) {
            uint32_t a[2][4];
            #pragma unroll
            for (int mt = 0; mt < 2; mt++)
                ldsm4(a[mt],
                      aoff + (uint32_t)((wm + mt * 16 + lr) * PAD + kw + lc) * 2);
            #pragma unroll
            for (int nt2 = 0; nt2 < 2; nt2++) {
                uint32_t b[4];
                ldsm4(b,
                      boff + (uint32_t)((wn + nt2 * 16 + lr) * PAD + kw + lc) * 2);
                mma16(c[0][2 * nt2],     a[0], b[0], b[2]);
                mma16(c[1][2 * nt2],     a[1], b[0], b[2]);
                mma16(c[0][2 * nt2 + 1], a[0], b[1], b[3]);
                mma16(c[1][2 * nt2 + 1], a[1], b[1], b[3]);
            }
        }
    }

    // Epilogue (R15): c[0]/c[1] = same row, adjacent cols -> vector stores.
    #pragma unroll
    for (int mt = 0; mt < 2; mt++) {
        #pragma unroll
        for (int nt = 0; nt < 4; nt++) {
            const int row0 = bm + wm + mt * 16 + g;
            const int row1 = row0 + 8;
            const int col  = bn + wn + nt * 8 + q * 2;   // even
            const float b0 = bias[col], b1 = bias[col + 1];
            float v0 = c[mt][nt][0] + b0;   // (row0, col)
            float v1 = c[mt][nt][1] + b1;   // (row0, col+1)
            float v2 = c[mt][nt][2] + b0;   // (row1, col)
            float v3 = c[mt][nt][3] + b1;   // (row1, col+1)
            if (MODE == 0) {
                const int which = col >> 10;
                const int cc = col & 1023;
                const int h  = cc >> 6;
                const int d  = cc & 63;     // even
                #pragma unroll
                for (int rr = 0; rr < 2; rr++) {
                    const int row = rr ? row1 : row0;
                    const float x0 = rr ? v2 : v0;
                    const float x1 = rr ? v3 : v1;
                    const int b  = row >> 11;
                    const int tt = row & 2047;
                    const size_t bh = (size_t)(b * NH + h);
                    if (which == 0) {
                        __half2 p = __floats2half2_rn(x0 * 0.125f, x1 * 0.125f);
                        *(__half2*)(g_Q + (bh * TT + tt) * HD + d) = p;
                    } else if (which == 1) {
                        __half2 p = __floats2half2_rn(x0, x1);
                        *(__half2*)(g_K + (bh * TT + tt) * HD + d) = p;
                    } else {
                        g_Vt[(bh * HD + d)     * TT + tt] = __float2half_rn(x0);
                        g_Vt[(bh * HD + d + 1) * TT + tt] = __float2half_rn(x1);
                    }
                }
            } else {
                *(float2*)(C + (size_t)row0 * CC + col) = make_float2(v0, v1);
                *(float2*)(C + (size_t)row1 * CC + col) = make_float2(v2, v3);
            }
        }
    }
}

// ---------------------------------------------------------------------------
// Flash attention (byte-identical to R11/R14 — proven best; do not touch).
// ---------------------------------------------------------------------------
#define KPH 72
#define VPH 72
#define PPH 72
#define FLASH_SMEM ((2*64*KPH + 2*64*VPH + 128*PPH) * 2)

__global__ __launch_bounds__(256) void flash16() {
    extern __shared__ __half fsm[];
    __half* Ks = fsm;                         // [2][64*KPH]
    __half* Vs = fsm + 2 * 64 * KPH;          // [2][64*VPH]
    __half* Ps = fsm + 2 * 64 * KPH + 2 * 64 * VPH;  // [128*PPH]

    const int tid  = threadIdx.x;
    const int lane = tid & 31;
    const int g    = lane >> 2;
    const int q    = lane & 3;
    const int w    = tid >> 5;
    const int wrow = w * 16;

    const int qt = (int)(gridDim.x - 1) - (int)blockIdx.x;
    const int bh = blockIdx.y;
    const int nkv = 2 * qt + 2;

    const __half* Qp = g_Q + ((size_t)bh * TT + qt * 128) * HD;
    uint32_t qa[4][4];
    #pragma unroll
    for (int ks = 0; ks < 4; ks++) {
        const int r0 = wrow + g, r1 = r0 + 8;
        const int c0 = ks * 16 + 2 * q;
        qa[ks][0] = *(const uint32_t*)(Qp + r0 * HD + c0);
        qa[ks][1] = *(const uint32_t*)(Qp + r1 * HD + c0);
        qa[ks][2] = *(const uint32_t*)(Qp + r0 * HD + c0 + 8);
        qa[ks][3] = *(const uint32_t*)(Qp + r1 * HD + c0 + 8);
    }

    float o[8][4];
    #pragma unroll
    for (int nt = 0; nt < 8; nt++)
        #pragma unroll
        for (int r = 0; r < 4; r++) o[nt][r] = 0.0f;
    float m0 = -INFINITY, m1 = -INFINITY, l0 = 0.0f, l1 = 0.0f;

    const uint32_t sK = smem_u32(Ks);
    const uint32_t sV = smem_u32(Vs);
    const int frow  = tid >> 2;
    const int fcolh = (tid & 3) * 16;

    auto fillkv = [&](int buf, int kti) {
        const __half* Kp = g_K + ((size_t)bh * TT + kti * 64 + frow) * HD + fcolh;
        const __half* Vp = g_Vt + ((size_t)bh * HD + frow) * TT + kti * 64 + fcolh;
        uint32_t dk = sK + (uint32_t)(buf * 64 * KPH + frow * KPH + fcolh) * 2;
        uint32_t dv = sV + (uint32_t)(buf * 64 * VPH + frow * VPH + fcolh) * 2;
        cp16(dk,      Kp);
        cp16(dk + 16, Kp + 8);
        cp16(dv,      Vp);
        cp16(dv + 16, Vp + 8);
    };

    fillkv(0, 0); CP_COMMIT();

    for (int ktt = 0; ktt < nkv; ktt++) {
        if (ktt + 1 < nkv) fillkv((ktt + 1) & 1, ktt + 1);
        CP_COMMIT();
        CP_WAIT(1);
        __syncthreads();

        const bool full_skip = (ktt * 64) > (qt * 128 + wrow + 15);
        if (!full_skip) {
            const uint32_t* Kb = (const uint32_t*)(Ks + (ktt & 1) * 64 * KPH);
            const uint32_t* Vb = (const uint32_t*)(Vs + (ktt & 1) * 64 * VPH);

            float s[8][4];
            #pragma unroll
            for (int nt = 0; nt < 8; nt++)
                #pragma unroll
                for (int r = 0; r < 4; r++) s[nt][r] = 0.0f;

            #pragma unroll
            for (int ks = 0; ks < 4; ks++) {
                #pragma unroll
                for (int nt = 0; nt < 8; nt++) {
                    uint32_t b0 = Kb[(nt * 8 + g) * 36 + ks * 8 + q];
                    uint32_t b1 = Kb[(nt * 8 + g) * 36 + ks * 8 + q + 4];
                    mma16(s[nt], qa[ks], b0, b1);
                }
            }

            const int rowg0 = qt * 128 + wrow + g;
            const int rowg1 = rowg0 + 8;
            if (ktt * 64 + 63 > qt * 128 + wrow) {
                #pragma unroll
                for (int nt = 0; nt < 8; nt++) {
                    const int c0 = ktt * 64 + nt * 8 + 2 * q;
                    if (c0     > rowg0) s[nt][0] = -INFINITY;
                    if (c0 + 1 > rowg0) s[nt][1] = -INFINITY;
                    if (c0     > rowg1) s[nt][2] = -INFINITY;
                    if (c0 + 1 > rowg1) s[nt][3] = -INFINITY;
                }
            }

            float mx0 = -INFINITY, mx1 = -INFINITY;
            #pragma unroll
            for (int nt = 0; nt < 8; nt++) {
                mx0 = fmaxf(mx0, fmaxf(s[nt][0], s[nt][1]));
                mx1 = fmaxf(mx1, fmaxf(s[nt][2], s[nt][3]));
            }
            mx0 = fmaxf(mx0, __shfl_xor_sync(0xffffffffu, mx0, 1));
            mx0 = fmaxf(mx0, __shfl_xor_sync(0xffffffffu, mx0, 2));
            mx1 = fmaxf(mx1, __shfl_xor_sync(0xffffffffu, mx1, 1));
            mx1 = fmaxf(mx1, __shfl_xor_sync(0xffffffffu, mx1, 2));

            float mn0 = fmaxf(m0, mx0), mn1 = fmaxf(m1, mx1);
            float corr0 = __expf(m0 - mn0), corr1 = __expf(m1 - mn1);
            m0 = mn0; m1 = mn1;

            float rs0 = 0.0f, rs1 = 0.0f;
            #pragma unroll
            for (int nt = 0; nt < 8; nt++) {
                s[nt][0] = __expf(s[nt][0] - m0); rs0 += s[nt][0];
                s[nt][1] = __expf(s[nt][1] - m0); rs0 += s[nt][1];
                s[nt][2] = __expf(s[nt][2] - m1); rs1 += s[nt][2];
                s[nt][3] = __expf(s[nt][3] - m1); rs1 += s[nt][3];
            }
            rs0 += __shfl_xor_sync(0xffffffffu, rs0, 1);
            rs0 += __shfl_xor_sync(0xffffffffu, rs0, 2);
            rs1 += __shfl_xor_sync(0xffffffffu, rs1, 1);
            rs1 += __shfl_xor_sync(0xffffffffu, rs1, 2);
            l0 = l0 * corr0 + rs0;
            l1 = l1 * corr1 + rs1;

            #pragma unroll
            for (int nt = 0; nt < 8; nt++) {
                o[nt][0] *= corr0; o[nt][1] *= corr0;
                o[nt][2] *= corr1; o[nt][3] *= corr1;
            }

            uint32_t* Pu = (uint32_t*)Ps;
            #pragma unroll
            for (int nt = 0; nt < 8; nt++) {
                const int cw = (nt * 8 + 2 * q) >> 1;
                __half2 p0 = __floats2half2_rn(s[nt][0], s[nt][1]);
                __half2 p1 = __floats2half2_rn(s[nt][2], s[nt][3]);
                Pu[(wrow + g)     * 36 + cw] = h2u(p0);
                Pu[(wrow + g + 8) * 36 + cw] = h2u(p1);
            }

            #pragma unroll
            for (int kk = 0; kk < 4; kk++) {
                uint32_t a[4];
                a[0] = Pu[(wrow + g)     * 36 + kk * 8 + q];
                a[1] = Pu[(wrow + g + 8) * 36 + kk * 8 + q];
                a[2] = Pu[(wrow + g)     * 36 + kk * 8 + q + 4];
                a[3] = Pu[(wrow + g + 8) * 36 + kk * 8 + q + 4];
                #pragma unroll
                for (int nt = 0; nt < 8; nt++) {
                    uint32_t b0 = Vb[(nt * 8 + g) * 36 + kk * 8 + q];
                    uint32_t b1 = Vb[(nt * 8 + g) * 36 + kk * 8 + q + 4];
                    mma16(o[nt], a, b0, b1);
                }
            }
        }
        __syncthreads();
    }

    const float inv0 = 1.0f / l0, inv1 = 1.0f / l1;
    const int b = bh >> 4;
    const int h = bh & 15;
    __half* obase = g_O + ((size_t)b * TT + qt * 128) * CC + h * HD;
    const int r0 = wrow + g, r1 = r0 + 8;
    #pragma unroll
    for (int nt = 0; nt < 8; nt++) {
        const int col = nt * 8 + 2 * q;
        __half2 v0 = __floats2half2_rn(o[nt][0] * inv0, o[nt][1] * inv0);
        __half2 v1 = __floats2half2_rn(o[nt][2] * inv1, o[nt][3] * inv1);
        *(__half2*)(obase + (size_t)r0 * CC + col) = v0;
        *(__half2*)(obase + (size_t)r1 * CC + col) = v1;
    }
}

// ---------------------------------------------------------------------------
extern "C" void kernel_launch(void* const* d_in, const int* in_sizes, int n_in,
                              void* d_out, int out_size) {
    const float* x     = (const float*)d_in[0];
    const float* W_qkv = (const float*)d_in[1];
    const float* b_qkv = (const float*)d_in[2];
    const float* W_out = (const float*)d_in[3];
    const float* b_out = (const float*)d_in[4];
    float* out = (float*)d_out;

    cudaFuncSetAttribute(flash16,
                         cudaFuncAttributeMaxDynamicSharedMemorySize,
                         FLASH_SMEM);
    cudaFuncSetAttribute(gemm16<0>,
                         cudaFuncAttributeMaxDynamicSharedMemorySize,
                         GEMM_SMEM);
    cudaFuncSetAttribute(gemm16<1>,
                         cudaFuncAttributeMaxDynamicSharedMemorySize,
                         GEMM_SMEM);

    // single merged prep launch
    prep<<<PREP_BLOCKS, 256>>>(x, W_qkv, W_out);

    dim3 gQKV(N_QKV / 128, MM / 128);      // 24 x 64
    gemm16<0><<<gQKV, 512, GEMM_SMEM>>>(b_qkv, nullptr);

    dim3 gFA(TT / 128, BB * NH);           // 16 x 64
    flash16<<<gFA, 256, FLASH_SMEM>>>();

    dim3 gOUT(CC / 128, MM / 128);         // 8 x 64
    gemm16<1><<<gOUT, 512, GEMM_SMEM>>>(b_out, out);
}